// round 15
// baseline (speedup 1.0000x reference)
#include <cuda_runtime.h>
#include <cstdint>

// ---------------------------------------------------------------------------
// ProposalCaffe: 64x64 feature map, 9 anchors, stride 16, img 1024x1024.
// 5 launches:
//  1) decode(+hist) + cut selection (last block)
//  2) compact + local bitonic sort (2 blocks x 4096, register/shfl steps)
//  3) merge finisher (fused j=4096 step on load) + gather
//  4) phase-A mask + fused pipelined scanA (last block)
//  5) phase-B mask + catchup + scanB (early-out when A picked 300)
// ---------------------------------------------------------------------------

#define H 64
#define W 64
#define A 9
#define NPROP (H * W * A)        // 36864
#define NBLK 36                  // NPROP / 1024
#define NCAND 8192
#define PRE_NMS 6000
#define POST_NMS 300
#define MASK_W 94                // ceil(6000/64)
#define CHUNKA 32                // phase-A chunk count (2048 boxes)
#define MA_BLOCKS 33             // 33*16 = 528 phase-A tiles
#define PB_TILES 4465            // 94*95/2
#define PB_PER 5
#define PB_BLOCKS 893

typedef unsigned long long ull;

__device__ float4 g_props[NPROP];
__device__ ull    g_keys[NPROP];
__device__ ull    g_sort[NCAND];
__device__ float4 g_top[PRE_NMS];
__device__ unsigned int g_fin32[192];
__device__ ull    g_mask[(size_t)PRE_NMS * MASK_W];  // 4.5 MB
__device__ int    g_histblk[NBLK * 256];
__device__ int    g_cut;
// phase A -> B handoff
__device__ ull    g_keptm[CHUNKA];
__device__ int    g_pick[POST_NMS];
__device__ int    g_np;
__device__ int    g_done;
// last-block counters (self-resetting each run)
__device__ int    g_ctrP = 0;
__device__ int    g_ctrA = 0;
__device__ int    g_ctrB = 0;

// Anchor table (exact integers; numpy banker's rounding applied)
__constant__ float c_anchors[A * 4] = {
    -84.f,  -40.f,  99.f,  55.f,
   -176.f,  -88.f, 191.f, 103.f,
   -360.f, -184.f, 375.f, 199.f,
    -56.f,  -56.f,  71.f,  71.f,
   -120.f, -120.f, 135.f, 135.f,
   -248.f, -248.f, 263.f, 263.f,
    -36.f,  -80.f,  51.f,  95.f,
    -80.f, -168.f,  95.f, 183.f,
   -168.f, -344.f, 183.f, 359.f,
};

__device__ __forceinline__ ull fin_word(int w) {
    return ((ull)g_fin32[2 * w + 1] << 32) | g_fin32[2 * w];
}

// ---------------------------------------------------------------------------
// Register-resident bitonic helpers. Each warp owns a 64-element segment:
// v0 = elem[seg*64 + l], v1 = elem[seg*64 + 32 + l]. g0 = global index of v0.
// Runs steps j = jstart..1 of phase k (j<=32 only).
// ---------------------------------------------------------------------------
__device__ __forceinline__ ull shflx64(ull v, int j) {
    unsigned lo = __shfl_xor_sync(0xffffffffu, (unsigned)v, j);
    unsigned hi = __shfl_xor_sync(0xffffffffu, (unsigned)(v >> 32), j);
    return ((ull)hi << 32) | lo;
}

__device__ __forceinline__ void reg_steps(ull& v0, ull& v1, int g0, int k, int jstart) {
    int l = g0 & 31;
    bool up0 = ((g0 & k) == 0);
    bool up1 = (((g0 + 32) & k) == 0);
    if (jstart == 32) {
        // pair (i, i+32): in-thread; direction = up0 (j < k so same subblock)
        ull mn = v0 < v1 ? v0 : v1, mx = v0 ^ v1 ^ mn;
        v0 = up0 ? mn : mx; v1 = up0 ? mx : mn;
    }
    for (int j = (jstart == 32 ? 16 : jstart); j > 0; j >>= 1) {
        bool lower = ((l & j) == 0);
        ull o0 = shflx64(v0, j);
        ull mn0 = v0 < o0 ? v0 : o0, mx0 = v0 ^ o0 ^ mn0;
        v0 = (lower == up0) ? mn0 : mx0;
        ull o1 = shflx64(v1, j);
        ull mn1 = v1 < o1 ? v1 : o1, mx1 = v1 ^ o1 ^ mn1;
        v1 = (lower == up1) ? mn1 : mx1;
    }
}

// ---------------------------------------------------------------------------
// K1: decode + per-block hist; last block selects the 16-bit cut.
// ---------------------------------------------------------------------------
__global__ void k_props(const float* __restrict__ scores,
                        const float* __restrict__ deltas) {
    __shared__ int sh[256];
    __shared__ int s_B, s_lt, s_last;
    int t = threadIdx.x;
    if (t < 256) sh[t] = 0;
    __syncthreads();

    int tid = blockIdx.x * 1024 + t;
    {
        int a = tid % A;
        int pix = tid / A;
        int x = pix % W;
        int y = pix / W;

        float s = scores[pix * (2 * A) + A + a];
        float4 dv4 = reinterpret_cast<const float4*>(deltas)[tid];
        float dx = dv4.x, dy = dv4.y, dw = dv4.z, dh = dv4.w;

        float sx = (float)(x * 16);
        float sy = (float)(y * 16);
        float ax1 = c_anchors[a * 4 + 0] + sx;
        float ay1 = c_anchors[a * 4 + 1] + sy;
        float ax2 = c_anchors[a * 4 + 2] + sx;
        float ay2 = c_anchors[a * 4 + 3] + sy;

        float aw = ax2 - ax1 + 1.0f;
        float ah = ay2 - ay1 + 1.0f;
        float acx = ax1 + 0.5f * aw;
        float acy = ay1 + 0.5f * ah;

        float pcx = dx * aw + acx;
        float pcy = dy * ah + acy;
        float pw = expf(dw) * aw;
        float ph = expf(dh) * ah;

        float x1 = fminf(fmaxf(pcx - 0.5f * pw, 0.0f), 1023.0f);
        float y1 = fminf(fmaxf(pcy - 0.5f * ph, 0.0f), 1023.0f);
        float x2 = fminf(fmaxf(pcx + 0.5f * pw, 0.0f), 1023.0f);
        float y2 = fminf(fmaxf(pcy + 0.5f * ph, 0.0f), 1023.0f);

        g_props[tid] = make_float4(x1, y1, x2, y2);

        bool valid = ((x2 - x1 + 1.0f) >= 16.0f) && ((y2 - y1 + 1.0f) >= 16.0f);
        float ms = valid ? s : __int_as_float(0xff800000);  // -inf

        unsigned int bits = __float_as_uint(ms);
        unsigned int u = (bits & 0x80000000u) ? ~bits : (bits | 0x80000000u);
        unsigned int k = ~u;  // ascending k == descending score
        g_keys[tid] = ((ull)k << 32) | (unsigned int)tid;
        atomicAdd(&sh[k >> 24], 1);
    }
    __syncthreads();
    if (t < 256) g_histblk[blockIdx.x * 256 + t] = sh[t];

    // last-block election
    __threadfence();
    __syncthreads();
    if (t == 0) s_last = (atomicAdd(&g_ctrP, 1) == NBLK - 1);
    __syncthreads();
    if (!s_last) return;
    if (t == 0) g_ctrP = 0;
    __threadfence();

    // ---- select 16-bit cut ----
    if (t < 256) {
        int s = 0;
        #pragma unroll
        for (int b = 0; b < NBLK; b++) s += g_histblk[b * 256 + t];
        sh[t] = s;
    }
    __syncthreads();
    if (t == 0) {
        int cum = 0, B = 255, lt = 0;
        for (int b = 0; b < 256; b++) {
            int c = sh[b];
            if (cum + c >= PRE_NMS) { B = b; lt = cum; break; }
            cum += c;
        }
        s_B = B; s_lt = lt;
    }
    __syncthreads();
    int B = s_B;
    if (t < 256) sh[t] = 0;
    __syncthreads();
    for (int i = t; i < NPROP; i += 1024) {
        unsigned int k = (unsigned int)(g_keys[i] >> 32);
        if ((int)(k >> 24) == B) atomicAdd(&sh[(k >> 16) & 255], 1);
    }
    __syncthreads();
    if (t == 0) {
        int cum = s_lt, B2 = 255;
        for (int b = 0; b < 256; b++) {
            cum += sh[b];
            if (cum >= PRE_NMS) { B2 = b; break; }
        }
        g_cut = (B << 8) | B2;
    }
}

// ---------------------------------------------------------------------------
// K2: fused compact (per-block half of g_keys) + local bitonic sort of 4096.
// Compaction order within the block is arbitrary: keys are distinct, so the
// sorted result is identical regardless of input permutation.
// ---------------------------------------------------------------------------
__global__ void k_sort_local() {
    __shared__ ull s[4096];
    __shared__ int s_cnt;
    int t = threadIdx.x;
    int base = blockIdx.x * 4096;
    #pragma unroll
    for (int q = 0; q < 4; q++) s[t + q * 1024] = ~0ULL;
    if (t == 0) s_cnt = 0;
    __syncthreads();

    int cut = g_cut;
    int kbeg = blockIdx.x * (NPROP / 2);
    for (int i = kbeg + t; i < kbeg + NPROP / 2; i += 1024) {
        ull key = g_keys[i];
        bool take = ((int)(key >> 48) <= cut);
        unsigned int m = __ballot_sync(0xffffffffu, take);
        int b0 = 0;
        if ((t & 31) == 0 && m) b0 = atomicAdd(&s_cnt, __popc(m));
        b0 = __shfl_sync(0xffffffffu, b0, 0);
        if (take) {
            int pos = b0 + __popc(m & ((1u << (t & 31)) - 1u));
            if (pos < 4096) s[pos] = key;
        }
    }
    __syncthreads();

    int w = t >> 5, l = t & 31;
    int sA = 2 * w, sB = 2 * w + 1;
    int gA = base + sA * 64 + l, gB = base + sB * 64 + l;
    ull a0 = s[sA * 64 + l], a1 = s[sA * 64 + 32 + l];
    ull b0 = s[sB * 64 + l], b1 = s[sB * 64 + 32 + l];

    // phases k=2..64 entirely in registers (no barriers)
    for (int k = 2; k <= 64; k <<= 1) {
        int js = (k == 64) ? 32 : (k >> 1);
        reg_steps(a0, a1, gA, k, js);
        reg_steps(b0, b1, gB, k, js);
    }
    s[sA * 64 + l] = a0; s[sA * 64 + 32 + l] = a1;
    s[sB * 64 + l] = b0; s[sB * 64 + 32 + l] = b1;
    __syncthreads();

    // phases k=128..4096: j>=64 in smem, j<=32 in registers
    for (int k = 128; k <= 4096; k <<= 1) {
        for (int j = k >> 1; j >= 64; j >>= 1) {
            #pragma unroll
            for (int q = 0; q < 2; q++) {
                int p = t + q * 1024;
                int i = 2 * p - (p & (j - 1));
                int ii = i + j;
                bool up = (((base + i) & k) == 0);
                ull va = s[i], vb = s[ii];
                if ((va > vb) == up) { s[i] = vb; s[ii] = va; }
            }
            __syncthreads();
        }
        a0 = s[sA * 64 + l]; a1 = s[sA * 64 + 32 + l];
        b0 = s[sB * 64 + l]; b1 = s[sB * 64 + 32 + l];
        reg_steps(a0, a1, gA, k, 32);
        reg_steps(b0, b1, gB, k, 32);
        if (k < 4096) {
            s[sA * 64 + l] = a0; s[sA * 64 + 32 + l] = a1;
            s[sB * 64 + l] = b0; s[sB * 64 + 32 + l] = b1;
            __syncthreads();
        }
    }
    g_sort[gA] = a0; g_sort[gA + 32] = a1;
    g_sort[gB] = b0; g_sort[gB + 32] = b1;
}

// ---------------------------------------------------------------------------
// K3: final merge. The k=8192, j=4096 step is fused into the load (block 0
// takes min of the halves, block 1 takes max). Then j=2048..64 in smem,
// j<=32 in registers, gather fused (all directions ascending).
// ---------------------------------------------------------------------------
__device__ __forceinline__ void emit_top(ull key, int g, int t) {
    bool in = (g < PRE_NMS);
    if (in) g_top[g] = g_props[(unsigned int)(key & 0xFFFFFFFFu)];
    bool fin = in && ((key >> 32) <= 0x7FFFFFFFull);
    unsigned int m = __ballot_sync(0xffffffffu, fin);
    if ((t & 31) == 0) {
        int wi = g >> 5;
        if (wi < 188) g_fin32[wi] = m;
    }
}

__global__ void k_merge_s() {
    __shared__ ull s[4096];
    int t = threadIdx.x;
    int base = blockIdx.x * 4096;
    #pragma unroll
    for (int q = 0; q < 4; q++) {
        int il = t + q * 1024;
        ull x = g_sort[il], y = g_sort[il + 4096];
        ull mn = x < y ? x : y;
        s[il] = blockIdx.x ? (x ^ y ^ mn) : mn;
    }
    __syncthreads();
    for (int j = 2048; j >= 64; j >>= 1) {
        #pragma unroll
        for (int q = 0; q < 2; q++) {
            int p = t + q * 1024;
            int i = 2 * p - (p & (j - 1));
            int ii = i + j;
            ull va = s[i], vb = s[ii];
            if (va > vb) { s[i] = vb; s[ii] = va; }  // ascending
        }
        __syncthreads();
    }
    int w = t >> 5, l = t & 31;
    int sA = 2 * w, sB = 2 * w + 1;
    int gA = base + sA * 64 + l, gB = base + sB * 64 + l;
    ull a0 = s[sA * 64 + l], a1 = s[sA * 64 + 32 + l];
    ull b0 = s[sB * 64 + l], b1 = s[sB * 64 + 32 + l];
    reg_steps(a0, a1, gA, 8192, 32);
    reg_steps(b0, b1, gB, 8192, 32);
    emit_top(a0, gA, t);
    emit_top(a1, gA + 32, t);
    emit_top(b0, gB, t);
    emit_top(b1, gB + 32, t);
}

// ---------------------------------------------------------------------------
// IoU mask for one 64x64 tile; colb preloaded by caller.
// ---------------------------------------------------------------------------
__device__ __forceinline__ void mask_rows(const float4* colb, int rb, int cb,
                                          int row_n, int col_n, int t64) {
    if (t64 < row_n) {
        int i = rb * 64 + t64;
        float4 b = g_top[i];
        float area_i = (b.z - b.x + 1.0f) * (b.w - b.y + 1.0f);
        ull bits = 0ULL;
        int start = (rb == cb) ? (t64 + 1) : 0;
        for (int c = start; c < col_n; c++) {
            float4 o = colb[c];
            float xx1 = fmaxf(b.x, o.x);
            float yy1 = fmaxf(b.y, o.y);
            float xx2 = fminf(b.z, o.z);
            float yy2 = fminf(b.w, o.w);
            float iw = fmaxf(xx2 - xx1 + 1.0f, 0.0f);
            float ih = fmaxf(yy2 - yy1 + 1.0f, 0.0f);
            float inter = iw * ih;
            float area_o = (o.z - o.x + 1.0f) * (o.w - o.y + 1.0f);
            float iou = inter / (area_i + area_o - inter);
            if (iou > 0.5f) bits |= (1ULL << c);
        }
        g_mask[(size_t)i * MASK_W + cb] = bits;
    }
}

// ---------------------------------------------------------------------------
// K4: phase-A mask (33 blocks x 16 tiles) + fused pipelined scanA (last blk).
// scanA per chunk: warp0 greedy inner loop; warps1-2 prefetch diag(c+1);
// warps3-4 prefetch this chunk's word c+1 (patch source) -> smem; warps>=5
// background full-width OR of chunk c-1's kept rows into s_remv.
// Patch computed from smem (LDS) instead of exposed L2 gather.
// ---------------------------------------------------------------------------
__global__ void k_maskA_scanA(float* __restrict__ out) {
    __shared__ float4 colb[16][64];
    __shared__ int s_last;
    int t = threadIdx.x;
    int lt = t >> 6, t64 = t & 63;

    int tile = blockIdx.x * 16 + lt;
    int rb = 0, rem = tile;
    while (rem >= (CHUNKA - rb)) { rem -= (CHUNKA - rb); rb++; }
    int cb = rb + rem;
    colb[lt][t64] = g_top[cb * 64 + t64];
    __syncthreads();
    mask_rows(colb[lt], rb, cb, 64, 64, t64);

    __threadfence();
    __syncthreads();
    if (t == 0) s_last = (atomicAdd(&g_ctrA, 1) == MA_BLOCKS - 1);
    __syncthreads();
    if (!s_last) return;
    if (t == 0) g_ctrA = 0;
    __threadfence();

    // ---- pipelined scanA ----
    __shared__ unsigned int s_remv[64];     // 32 ull words as lo/hi pairs
    __shared__ ull s_diag[2][64];
    __shared__ ull s_nextcol[64];
    __shared__ ull s_keptm2[2];
    __shared__ int s_flag, s_np;
    __shared__ int s_pick[POST_NMS];

    int lane = t & 31, wid = t >> 5;
    for (int i = t; i < POST_NMS * 4; i += 1024) out[i] = 0.0f;
    if (t < 64) {
        s_remv[t] = 0u;
        s_diag[0][t] = g_mask[(size_t)t * MASK_W];
    }
    if (t == 0) { s_keptm2[0] = 0; s_keptm2[1] = 0; s_flag = 0; }
    __syncthreads();

    ull f0 = (wid == 0) ? fin_word(lane) : 0ULL;
    ull patch = 0ULL;   // warp0-resident
    int np = 0;
    bool done = false;

    for (int c = 0; c < CHUNKA; c++) {
        int buf = c & 1;
        ull keptm = 0ULL;
        if (wid == 0) {
            ull d0 = s_diag[buf][lane];
            ull d1 = s_diag[buf][lane + 32];
            ull r = ((((ull)s_remv[2 * c + 1]) << 32) | s_remv[2 * c]) | patch;
            ull fw = __shfl_sync(0xffffffffu, f0, c);
            ull avail = ~r;
            while (avail) {
                int b = __ffsll((long long)avail) - 1;
                keptm |= (1ULL << b);
                if ((fw >> b) & 1ULL) {
                    if (lane == 0) s_pick[np] = c * 64 + b;
                    np++;
                    if (np == POST_NMS) { done = true; break; }
                }
                ull dv = __shfl_sync(0xffffffffu, (b < 32) ? d0 : d1, b & 31);
                avail &= ~dv;
                avail &= ~(1ULL << b);
            }
            if (lane == 0) {
                g_keptm[c] = keptm;
                s_keptm2[buf] = keptm;
                if (done) s_flag = 1;
            }
        } else if (t < 96) {
            if (c + 1 < CHUNKA) {
                int idx = t - 32;
                s_diag[buf ^ 1][idx] =
                    g_mask[(size_t)((c + 1) * 64 + idx) * MASK_W + (c + 1)];
            }
        } else if (t < 160) {
            int idx = t - 96;
            s_nextcol[idx] = g_mask[(size_t)(c * 64 + idx) * MASK_W + (c + 1)];
        } else {
            if (c >= 1) {
                ull km = s_keptm2[buf ^ 1];  // chunk c-1 kept rows
                int wd = (t - 160) & 31;
                int slot = (t - 160) >> 5;   // 0..26
                ull acc = 0;
                #pragma unroll
                for (int u = 0; u < 3; u++) {
                    int sb = slot + u * 27;
                    if (sb < 64 && ((km >> sb) & 1ULL))
                        acc |= g_mask[(size_t)((c - 1) * 64 + sb) * MASK_W + wd];
                }
                if (acc) {
                    atomicOr(&s_remv[2 * wd], (unsigned int)acc);
                    atomicOr(&s_remv[2 * wd + 1], (unsigned int)(acc >> 32));
                }
            }
        }
        __syncthreads();
        if (s_flag) break;
        if (wid == 0) {
            // patch for chunk c+1: kept rows of chunk c, word c+1 (from smem)
            ull pp = 0;
            if ((keptm >> lane) & 1ULL) pp = s_nextcol[lane];
            if ((keptm >> (lane + 32)) & 1ULL) pp |= s_nextcol[lane + 32];
            unsigned int lo = __reduce_or_sync(0xffffffffu, (unsigned int)pp);
            unsigned int hi = __reduce_or_sync(0xffffffffu, (unsigned int)(pp >> 32));
            patch = ((ull)hi << 32) | lo;
        }
        __syncthreads();   // protect s_nextcol against next iteration's writers
    }

    if (wid == 0 && lane == 0) {
        s_np = np;
        g_np = np;
        g_done = done ? 1 : 0;
    }
    __syncthreads();
    int N = s_np;
    const float inv = 1.0f / 1024.0f;
    if (s_flag) {
        for (int p = t; p < N; p += 1024) {
            int i = s_pick[p];
            float4 b = g_top[i];
            out[p * 4 + 0] = b.x * inv;
            out[p * 4 + 1] = b.y * inv;
            out[p * 4 + 2] = b.z * inv;
            out[p * 4 + 3] = b.w * inv;
        }
    } else {
        for (int p = t; p < N; p += 1024) g_pick[p] = s_pick[p];
    }
}

// ---------------------------------------------------------------------------
// K5: phase-B mask + catchup + scanB fused; hot path (g_done) returns
// immediately WITHOUT touching the election counter.
// ---------------------------------------------------------------------------
__global__ void k_phaseB(float* __restrict__ out) {
    __shared__ float4 colb[64];
    __shared__ int s_last;
    int t = threadIdx.x;
    if (g_done) return;   // hot path: no mask work, no atomics

    for (int e = 0; e < PB_PER; e++) {
        int tile = blockIdx.x * PB_PER + e;
        if (tile >= PB_TILES) break;
        int rb = 0, rem = tile;
        while (rem >= (MASK_W - rb)) { rem -= (MASK_W - rb); rb++; }
        int cb = rb + rem;
        if (rb < CHUNKA && cb < CHUNKA) continue;  // phase-A square done
        int row_n = min(PRE_NMS - rb * 64, 64);
        int col_n = min(PRE_NMS - cb * 64, 64);
        __syncthreads();
        if (t < col_n) colb[t] = g_top[cb * 64 + t];
        __syncthreads();
        mask_rows(colb, rb, cb, row_n, col_n, t);
    }

    __threadfence();
    __syncthreads();
    if (t == 0) s_last = (atomicAdd(&g_ctrB, 1) == PB_BLOCKS - 1);
    __syncthreads();
    if (!s_last) return;
    if (t == 0) g_ctrB = 0;
    __threadfence();

    // ---- catchup: OR phase-A kept rows' words 32..93 ----
    __shared__ unsigned int accw[124];   // 62 ull as lo/hi
    __shared__ short rows[2048];
    __shared__ int s_n;
    __shared__ int s_pick[POST_NMS];
    if (t == 0) s_n = 0;
    if (t < 62) { accw[2 * t] = 0; accw[2 * t + 1] = 0; }
    __syncthreads();
    if (t < CHUNKA) {
        ull km = g_keptm[t];
        int n = __popcll(km);
        int off = atomicAdd(&s_n, n);
        while (km) {
            int b = __ffsll((long long)km) - 1; km &= km - 1;
            rows[off++] = (short)(t * 64 + b);
        }
    }
    __syncthreads();
    int K = s_n;
    for (int idx = t; idx < K * 62; idx += 64) {
        int rr = idx / 62, w = idx % 62;
        ull v = g_mask[(size_t)rows[rr] * MASK_W + 32 + w];
        if (v) {
            atomicOr(&accw[2 * w], (unsigned int)v);
            atomicOr(&accw[2 * w + 1], (unsigned int)(v >> 32));
        }
    }
    int np0 = g_np;
    for (int p = t; p < np0; p += 64) s_pick[p] = g_pick[p];
    __syncthreads();

    // ---- scanB (warp 0 only) ----
    if (t < 32) {
        int lane = t;
        int np = np0;
        ull r1 = (((ull)accw[2 * lane + 1]) << 32) | accw[2 * lane];
        ull r2 = (lane + 64 < MASK_W)
            ? ((((ull)accw[2 * (lane + 32) + 1]) << 32) | accw[2 * (lane + 32)])
            : 0ULL;
        ull f1 = fin_word(lane + 32);
        ull f2 = (lane + 64 < MASK_W) ? fin_word(lane + 64) : 0ULL;

        bool done = false;
        for (int c = CHUNKA; c < MASK_W && !done; c++) {
            ull rw = (c < 64) ? r1 : r2;
            ull r = __shfl_sync(0xffffffffu, rw, c & 31);
            ull fwv = (c < 64) ? f1 : f2;
            ull fw = __shfl_sync(0xffffffffu, fwv, c & 31);

            int nrows = min(PRE_NMS - c * 64, 64);
            ull lim = (nrows == 64) ? ~0ULL : ((1ULL << nrows) - 1ULL);
            ull d0 = (lane < nrows)
                ? g_mask[(size_t)(c * 64 + lane) * MASK_W + c] : 0ULL;
            ull d1 = (lane + 32 < nrows)
                ? g_mask[(size_t)(c * 64 + lane + 32) * MASK_W + c] : 0ULL;

            ull avail = ~r & lim;
            ull keptm = 0ULL;
            while (avail) {
                int b = __ffsll((long long)avail) - 1;
                keptm |= (1ULL << b);
                if ((fw >> b) & 1ULL) {
                    if (lane == 0) s_pick[np] = c * 64 + b;
                    np++;
                    if (np == POST_NMS) { done = true; break; }
                }
                ull dv = __shfl_sync(0xffffffffu, (b < 32) ? d0 : d1, b & 31);
                avail &= ~dv;
                avail &= ~(1ULL << b);
            }

            if (!done) {
                ull km = keptm;
                while (km) {
                    int rr4[4]; int nr = 0;
                    #pragma unroll
                    for (int u = 0; u < 4; u++) {
                        if (km) { rr4[nr++] = __ffsll((long long)km) - 1; km &= km - 1; }
                    }
                    ull a1 = 0, a2 = 0;
                    #pragma unroll
                    for (int u = 0; u < 4; u++) {
                        if (u < nr) {
                            const ull* p = &g_mask[(size_t)(c * 64 + rr4[u]) * MASK_W];
                            a1 |= p[lane + 32];
                            if (lane + 64 < MASK_W) a2 |= p[lane + 64];
                        }
                    }
                    r1 |= a1; r2 |= a2;
                }
            }
        }

        __syncwarp();
        const float inv = 1.0f / 1024.0f;
        for (int p = lane; p < np; p += 32) {
            int i = s_pick[p];
            float4 b = g_top[i];
            out[p * 4 + 0] = b.x * inv;
            out[p * 4 + 1] = b.y * inv;
            out[p * 4 + 2] = b.z * inv;
            out[p * 4 + 3] = b.w * inv;
        }
    }
}

// ---------------------------------------------------------------------------
extern "C" void kernel_launch(void* const* d_in, const int* in_sizes, int n_in,
                              void* d_out, int out_size) {
    const float* scores = (const float*)d_in[0];
    const float* deltas = (const float*)d_in[1];
    float* out = (float*)d_out;

    k_props<<<NBLK, 1024>>>(scores, deltas);
    k_sort_local<<<2, 1024>>>();
    k_merge_s<<<2, 1024>>>();
    k_maskA_scanA<<<MA_BLOCKS, 1024>>>(out);
    k_phaseB<<<PB_BLOCKS, 64>>>(out);
}

// round 17
// speedup vs baseline: 1.0572x; 1.0572x over previous
#include <cuda_runtime.h>
#include <cstdint>

// ---------------------------------------------------------------------------
// ProposalCaffe: 64x64 feature map, 9 anchors, stride 16, img 1024x1024.
// 5 launches:
//  1) decode(+hist) + cut selection (last block)
//  2) compact + local bitonic sort (2 blocks x 4096, register/shfl steps)
//  3) merge finisher (fused j=4096 step on load) + gather
//  4) phase-A mask (520 blocks x 4 tiles, 64x64-chunk triangle) +
//     fused single-barrier pipelined scanA (elected last block, 256 thr)
//  5) phase-B mask + catchup + scanB (early-out when A picked 300)
// ---------------------------------------------------------------------------

#define H 64
#define W 64
#define A 9
#define NPROP (H * W * A)        // 36864
#define NBLK 36                  // NPROP / 1024
#define NCAND 8192
#define PRE_NMS 6000
#define POST_NMS 300
#define MASK_W 94                // ceil(6000/64)
#define CHUNKA 64                // phase-A chunk count (4096 boxes)
#define MA_TILES 2080            // 64*65/2
#define MA_BLOCKS 520            // 520*4 = 2080 tiles
#define PB_TILES 4465            // 94*95/2
#define PB_PER 5
#define PB_BLOCKS 893

typedef unsigned long long ull;

__device__ float4 g_props[NPROP];
__device__ ull    g_keys[NPROP];
__device__ ull    g_sort[NCAND];
__device__ float4 g_top[PRE_NMS];
__device__ unsigned int g_fin32[192];
__device__ ull    g_mask[(size_t)PRE_NMS * MASK_W];  // 4.5 MB
__device__ int    g_histblk[NBLK * 256];
__device__ int    g_cut;
// phase A -> B handoff
__device__ ull    g_keptm[CHUNKA];
__device__ int    g_pick[POST_NMS];
__device__ int    g_np;
__device__ int    g_done;
// last-block counters (self-resetting each run)
__device__ int    g_ctrP = 0;
__device__ int    g_ctrA = 0;
__device__ int    g_ctrB = 0;

// Anchor table (exact integers; numpy banker's rounding applied)
__constant__ float c_anchors[A * 4] = {
    -84.f,  -40.f,  99.f,  55.f,
   -176.f,  -88.f, 191.f, 103.f,
   -360.f, -184.f, 375.f, 199.f,
    -56.f,  -56.f,  71.f,  71.f,
   -120.f, -120.f, 135.f, 135.f,
   -248.f, -248.f, 263.f, 263.f,
    -36.f,  -80.f,  51.f,  95.f,
    -80.f, -168.f,  95.f, 183.f,
   -168.f, -344.f, 183.f, 359.f,
};

__device__ __forceinline__ ull fin_word(int w) {
    return ((ull)g_fin32[2 * w + 1] << 32) | g_fin32[2 * w];
}

// ---------------------------------------------------------------------------
// Register-resident bitonic helpers (unchanged from R8).
// ---------------------------------------------------------------------------
__device__ __forceinline__ ull shflx64(ull v, int j) {
    unsigned lo = __shfl_xor_sync(0xffffffffu, (unsigned)v, j);
    unsigned hi = __shfl_xor_sync(0xffffffffu, (unsigned)(v >> 32), j);
    return ((ull)hi << 32) | lo;
}

__device__ __forceinline__ void reg_steps(ull& v0, ull& v1, int g0, int k, int jstart) {
    int l = g0 & 31;
    bool up0 = ((g0 & k) == 0);
    bool up1 = (((g0 + 32) & k) == 0);
    if (jstart == 32) {
        ull mn = v0 < v1 ? v0 : v1, mx = v0 ^ v1 ^ mn;
        v0 = up0 ? mn : mx; v1 = up0 ? mx : mn;
    }
    for (int j = (jstart == 32 ? 16 : jstart); j > 0; j >>= 1) {
        bool lower = ((l & j) == 0);
        ull o0 = shflx64(v0, j);
        ull mn0 = v0 < o0 ? v0 : o0, mx0 = v0 ^ o0 ^ mn0;
        v0 = (lower == up0) ? mn0 : mx0;
        ull o1 = shflx64(v1, j);
        ull mn1 = v1 < o1 ? v1 : o1, mx1 = v1 ^ o1 ^ mn1;
        v1 = (lower == up1) ? mn1 : mx1;
    }
}

// ---------------------------------------------------------------------------
// K1: decode + per-block hist; last block selects the 16-bit cut.
// ---------------------------------------------------------------------------
__global__ void k_props(const float* __restrict__ scores,
                        const float* __restrict__ deltas) {
    __shared__ int sh[256];
    __shared__ int s_B, s_lt, s_last;
    int t = threadIdx.x;
    if (t < 256) sh[t] = 0;
    __syncthreads();

    int tid = blockIdx.x * 1024 + t;
    {
        int a = tid % A;
        int pix = tid / A;
        int x = pix % W;
        int y = pix / W;

        float s = scores[pix * (2 * A) + A + a];
        float4 dv4 = reinterpret_cast<const float4*>(deltas)[tid];
        float dx = dv4.x, dy = dv4.y, dw = dv4.z, dh = dv4.w;

        float sx = (float)(x * 16);
        float sy = (float)(y * 16);
        float ax1 = c_anchors[a * 4 + 0] + sx;
        float ay1 = c_anchors[a * 4 + 1] + sy;
        float ax2 = c_anchors[a * 4 + 2] + sx;
        float ay2 = c_anchors[a * 4 + 3] + sy;

        float aw = ax2 - ax1 + 1.0f;
        float ah = ay2 - ay1 + 1.0f;
        float acx = ax1 + 0.5f * aw;
        float acy = ay1 + 0.5f * ah;

        float pcx = dx * aw + acx;
        float pcy = dy * ah + acy;
        float pw = expf(dw) * aw;
        float ph = expf(dh) * ah;

        float x1 = fminf(fmaxf(pcx - 0.5f * pw, 0.0f), 1023.0f);
        float y1 = fminf(fmaxf(pcy - 0.5f * ph, 0.0f), 1023.0f);
        float x2 = fminf(fmaxf(pcx + 0.5f * pw, 0.0f), 1023.0f);
        float y2 = fminf(fmaxf(pcy + 0.5f * ph, 0.0f), 1023.0f);

        g_props[tid] = make_float4(x1, y1, x2, y2);

        bool valid = ((x2 - x1 + 1.0f) >= 16.0f) && ((y2 - y1 + 1.0f) >= 16.0f);
        float ms = valid ? s : __int_as_float(0xff800000);  // -inf

        unsigned int bits = __float_as_uint(ms);
        unsigned int u = (bits & 0x80000000u) ? ~bits : (bits | 0x80000000u);
        unsigned int k = ~u;  // ascending k == descending score
        g_keys[tid] = ((ull)k << 32) | (unsigned int)tid;
        atomicAdd(&sh[k >> 24], 1);
    }
    __syncthreads();
    if (t < 256) g_histblk[blockIdx.x * 256 + t] = sh[t];

    __threadfence();
    __syncthreads();
    if (t == 0) s_last = (atomicAdd(&g_ctrP, 1) == NBLK - 1);
    __syncthreads();
    if (!s_last) return;
    if (t == 0) g_ctrP = 0;
    __threadfence();

    // ---- select 16-bit cut ----
    if (t < 256) {
        int s = 0;
        #pragma unroll
        for (int b = 0; b < NBLK; b++) s += g_histblk[b * 256 + t];
        sh[t] = s;
    }
    __syncthreads();
    if (t == 0) {
        int cum = 0, B = 255, lt = 0;
        for (int b = 0; b < 256; b++) {
            int c = sh[b];
            if (cum + c >= PRE_NMS) { B = b; lt = cum; break; }
            cum += c;
        }
        s_B = B; s_lt = lt;
    }
    __syncthreads();
    int B = s_B;
    if (t < 256) sh[t] = 0;
    __syncthreads();
    for (int i = t; i < NPROP; i += 1024) {
        unsigned int k = (unsigned int)(g_keys[i] >> 32);
        if ((int)(k >> 24) == B) atomicAdd(&sh[(k >> 16) & 255], 1);
    }
    __syncthreads();
    if (t == 0) {
        int cum = s_lt, B2 = 255;
        for (int b = 0; b < 256; b++) {
            cum += sh[b];
            if (cum >= PRE_NMS) { B2 = b; break; }
        }
        g_cut = (B << 8) | B2;
    }
}

// ---------------------------------------------------------------------------
// K2: fused compact + local bitonic sort of 4096 (unchanged).
// ---------------------------------------------------------------------------
__global__ void k_sort_local() {
    __shared__ ull s[4096];
    __shared__ int s_cnt;
    int t = threadIdx.x;
    int base = blockIdx.x * 4096;
    #pragma unroll
    for (int q = 0; q < 4; q++) s[t + q * 1024] = ~0ULL;
    if (t == 0) s_cnt = 0;
    __syncthreads();

    int cut = g_cut;
    int kbeg = blockIdx.x * (NPROP / 2);
    for (int i = kbeg + t; i < kbeg + NPROP / 2; i += 1024) {
        ull key = g_keys[i];
        bool take = ((int)(key >> 48) <= cut);
        unsigned int m = __ballot_sync(0xffffffffu, take);
        int b0 = 0;
        if ((t & 31) == 0 && m) b0 = atomicAdd(&s_cnt, __popc(m));
        b0 = __shfl_sync(0xffffffffu, b0, 0);
        if (take) {
            int pos = b0 + __popc(m & ((1u << (t & 31)) - 1u));
            if (pos < 4096) s[pos] = key;
        }
    }
    __syncthreads();

    int w = t >> 5, l = t & 31;
    int sA = 2 * w, sB = 2 * w + 1;
    int gA = base + sA * 64 + l, gB = base + sB * 64 + l;
    ull a0 = s[sA * 64 + l], a1 = s[sA * 64 + 32 + l];
    ull b0 = s[sB * 64 + l], b1 = s[sB * 64 + 32 + l];

    for (int k = 2; k <= 64; k <<= 1) {
        int js = (k == 64) ? 32 : (k >> 1);
        reg_steps(a0, a1, gA, k, js);
        reg_steps(b0, b1, gB, k, js);
    }
    s[sA * 64 + l] = a0; s[sA * 64 + 32 + l] = a1;
    s[sB * 64 + l] = b0; s[sB * 64 + 32 + l] = b1;
    __syncthreads();

    for (int k = 128; k <= 4096; k <<= 1) {
        for (int j = k >> 1; j >= 64; j >>= 1) {
            #pragma unroll
            for (int q = 0; q < 2; q++) {
                int p = t + q * 1024;
                int i = 2 * p - (p & (j - 1));
                int ii = i + j;
                bool up = (((base + i) & k) == 0);
                ull va = s[i], vb = s[ii];
                if ((va > vb) == up) { s[i] = vb; s[ii] = va; }
            }
            __syncthreads();
        }
        a0 = s[sA * 64 + l]; a1 = s[sA * 64 + 32 + l];
        b0 = s[sB * 64 + l]; b1 = s[sB * 64 + 32 + l];
        reg_steps(a0, a1, gA, k, 32);
        reg_steps(b0, b1, gB, k, 32);
        if (k < 4096) {
            s[sA * 64 + l] = a0; s[sA * 64 + 32 + l] = a1;
            s[sB * 64 + l] = b0; s[sB * 64 + 32 + l] = b1;
            __syncthreads();
        }
    }
    g_sort[gA] = a0; g_sort[gA + 32] = a1;
    g_sort[gB] = b0; g_sort[gB + 32] = b1;
}

// ---------------------------------------------------------------------------
// K3: final merge + gather (unchanged).
// ---------------------------------------------------------------------------
__device__ __forceinline__ void emit_top(ull key, int g, int t) {
    bool in = (g < PRE_NMS);
    if (in) g_top[g] = g_props[(unsigned int)(key & 0xFFFFFFFFu)];
    bool fin = in && ((key >> 32) <= 0x7FFFFFFFull);
    unsigned int m = __ballot_sync(0xffffffffu, fin);
    if ((t & 31) == 0) {
        int wi = g >> 5;
        if (wi < 188) g_fin32[wi] = m;
    }
}

__global__ void k_merge_s() {
    __shared__ ull s[4096];
    int t = threadIdx.x;
    int base = blockIdx.x * 4096;
    #pragma unroll
    for (int q = 0; q < 4; q++) {
        int il = t + q * 1024;
        ull x = g_sort[il], y = g_sort[il + 4096];
        ull mn = x < y ? x : y;
        s[il] = blockIdx.x ? (x ^ y ^ mn) : mn;
    }
    __syncthreads();
    for (int j = 2048; j >= 64; j >>= 1) {
        #pragma unroll
        for (int q = 0; q < 2; q++) {
            int p = t + q * 1024;
            int i = 2 * p - (p & (j - 1));
            int ii = i + j;
            ull va = s[i], vb = s[ii];
            if (va > vb) { s[i] = vb; s[ii] = va; }
        }
        __syncthreads();
    }
    int w = t >> 5, l = t & 31;
    int sA = 2 * w, sB = 2 * w + 1;
    int gA = base + sA * 64 + l, gB = base + sB * 64 + l;
    ull a0 = s[sA * 64 + l], a1 = s[sA * 64 + 32 + l];
    ull b0 = s[sB * 64 + l], b1 = s[sB * 64 + 32 + l];
    reg_steps(a0, a1, gA, 8192, 32);
    reg_steps(b0, b1, gB, 8192, 32);
    emit_top(a0, gA, t);
    emit_top(a1, gA + 32, t);
    emit_top(b0, gB, t);
    emit_top(b1, gB + 32, t);
}

// ---------------------------------------------------------------------------
// IoU mask: division-free comparison with exact-borderline fallback.
// inter/un > 0.5  <=>  inter > 0.5*un  except within 1e-6 relative of the
// boundary, where we replicate the reference's float division exactly.
// ---------------------------------------------------------------------------
__device__ __forceinline__ void mask_rows(const float4* colb, int rb, int cb,
                                          int row_n, int col_n, int t64) {
    if (t64 < row_n) {
        int i = rb * 64 + t64;
        float4 b = g_top[i];
        float area_i = (b.z - b.x + 1.0f) * (b.w - b.y + 1.0f);
        ull bits = 0ULL;
        int start = (rb == cb) ? (t64 + 1) : 0;
        for (int c = start; c < col_n; c++) {
            float4 o = colb[c];
            float xx1 = fmaxf(b.x, o.x);
            float yy1 = fmaxf(b.y, o.y);
            float xx2 = fminf(b.z, o.z);
            float yy2 = fminf(b.w, o.w);
            float iw = fmaxf(xx2 - xx1 + 1.0f, 0.0f);
            float ih = fmaxf(yy2 - yy1 + 1.0f, 0.0f);
            float inter = iw * ih;
            float area_o = (o.z - o.x + 1.0f) * (o.w - o.y + 1.0f);
            float un = area_i + area_o - inter;
            float half_u = 0.5f * un;
            bool sup = inter > half_u;
            if (fabsf(inter - half_u) <= 1e-6f * un)   // borderline: exact path
                sup = (inter / un) > 0.5f;
            if (sup) bits |= (1ULL << c);
        }
        g_mask[(size_t)i * MASK_W + cb] = bits;
    }
}

// ---------------------------------------------------------------------------
// K4: phase-A mask (520 blocks x 256 thr, 4 tiles each over the 64x64-chunk
// triangle) + fused scanA on elected last block (256 thr, ONE barrier/chunk).
// Roles: warp0 greedy+patch; warp1 diag(c+1) prefetch; warp2 nextcol(c)
// prefetch; warps3-6 background full-width OR of chunk c-1 kept rows.
// ---------------------------------------------------------------------------
__global__ void k_maskA_scanA(float* __restrict__ out) {
    __shared__ float4 colb[4][64];
    __shared__ int s_last;
    int t = threadIdx.x;
    int grp = t >> 6, t64 = t & 63;

    int tile = blockIdx.x * 4 + grp;
    int rb = 0, rem = tile;
    while (rem >= (CHUNKA - rb)) { rem -= (CHUNKA - rb); rb++; }
    int cb = rb + rem;
    colb[grp][t64] = g_top[cb * 64 + t64];
    __syncthreads();
    mask_rows(colb[grp], rb, cb, 64, 64, t64);

    __threadfence();
    __syncthreads();
    if (t == 0) s_last = (atomicAdd(&g_ctrA, 1) == MA_BLOCKS - 1);
    __syncthreads();
    if (!s_last) return;
    if (t == 0) g_ctrA = 0;
    __threadfence();

    // ---- scanA ----
    __shared__ ull s_remv[CHUNKA];      // words 0..63
    __shared__ ull s_diag[2][64];
    __shared__ ull s_next[2][64];
    __shared__ ull s_keptm[2];
    __shared__ int s_flag, s_np;
    __shared__ int s_pick[POST_NMS];

    int lane = t & 31, wid = t >> 5;
    for (int i = t; i < POST_NMS * 4; i += 256) out[i] = 0.0f;
    if (t < CHUNKA) s_remv[t] = 0ULL;
    if (t < 64) s_diag[0][t] = g_mask[(size_t)t * MASK_W];
    if (t == 0) { s_keptm[0] = 0; s_keptm[1] = 0; s_flag = 0; }
    __syncthreads();

    ull f0 = 0, f1 = 0, kprev = 0;
    if (wid == 0) { f0 = fin_word(lane); f1 = fin_word(lane + 32); }
    int np = 0;
    bool done = false;

    for (int c = 0; c < CHUNKA; c++) {
        int buf = c & 1;
        if (wid == 0) {
            // patch: chunk c-1 kept rows' word c (loaded into s_next[buf^1])
            ull pp = 0;
            if ((kprev >> lane) & 1ULL) pp = s_next[buf ^ 1][lane];
            if ((kprev >> (lane + 32)) & 1ULL) pp |= s_next[buf ^ 1][lane + 32];
            unsigned lo = __reduce_or_sync(0xffffffffu, (unsigned)pp);
            unsigned hi = __reduce_or_sync(0xffffffffu, (unsigned)(pp >> 32));
            ull patch = ((ull)hi << 32) | lo;

            ull d0 = s_diag[buf][lane];
            ull d1 = s_diag[buf][lane + 32];
            ull r = s_remv[c] | patch;
            ull fwv = (c < 32) ? f0 : f1;
            ull fw = __shfl_sync(0xffffffffu, fwv, c & 31);
            ull avail = ~r, keptm = 0ULL;
            while (avail) {
                int b = __ffsll((long long)avail) - 1;
                keptm |= (1ULL << b);
                if ((fw >> b) & 1ULL) {
                    if (lane == 0) s_pick[np] = c * 64 + b;
                    np++;
                    if (np == POST_NMS) { done = true; break; }
                }
                ull dv = __shfl_sync(0xffffffffu, (b < 32) ? d0 : d1, b & 31);
                avail &= ~dv;
                avail &= ~(1ULL << b);
            }
            kprev = keptm;
            if (lane == 0) {
                g_keptm[c] = keptm;
                s_keptm[buf] = keptm;
                if (done) s_flag = 1;
            }
        } else if (wid == 1) {
            if (c + 1 < CHUNKA) {
                s_diag[buf ^ 1][lane] =
                    g_mask[(size_t)((c + 1) * 64 + lane) * MASK_W + (c + 1)];
                s_diag[buf ^ 1][lane + 32] =
                    g_mask[(size_t)((c + 1) * 64 + lane + 32) * MASK_W + (c + 1)];
            }
        } else if (wid == 2) {
            if (c + 1 < CHUNKA) {
                s_next[buf][lane] =
                    g_mask[(size_t)(c * 64 + lane) * MASK_W + (c + 1)];
                s_next[buf][lane + 32] =
                    g_mask[(size_t)(c * 64 + lane + 32) * MASK_W + (c + 1)];
            }
        } else if (t < 224) {   // wid 3..6: background OR of chunk c-1
            if (c >= 1) {
                int q = t - 96;                 // 0..127
                ull km = s_keptm[buf ^ 1];      // chunk c-1 kept rows
                int w = q & 63, rsl = q >> 6;   // word, row parity
                ull acc = 0;
                for (int u = 0; u < 32; u++) {
                    int sb = rsl + 2 * u;
                    if ((km >> sb) & 1ULL)
                        acc |= g_mask[(size_t)((c - 1) * 64 + sb) * MASK_W + w];
                }
                if (acc) atomicOr(&s_remv[w], acc);
            }
        }
        __syncthreads();
        if (s_flag) break;
    }

    if (wid == 0 && lane == 0) {
        s_np = np;
        g_np = np;
        g_done = done ? 1 : 0;
    }
    __syncthreads();
    int N = s_np;
    const float inv = 1.0f / 1024.0f;
    if (s_flag) {
        for (int p = t; p < N; p += 256) {
            int i = s_pick[p];
            float4 b = g_top[i];
            out[p * 4 + 0] = b.x * inv;
            out[p * 4 + 1] = b.y * inv;
            out[p * 4 + 2] = b.z * inv;
            out[p * 4 + 3] = b.w * inv;
        }
    } else {
        for (int p = t; p < N; p += 256) g_pick[p] = s_pick[p];
    }
}

// ---------------------------------------------------------------------------
// K5: phase-B mask + catchup + scanB fused; hot path returns immediately.
// ---------------------------------------------------------------------------
__global__ void k_phaseB(float* __restrict__ out) {
    __shared__ float4 colb[64];
    __shared__ int s_last;
    int t = threadIdx.x;
    if (g_done) return;

    for (int e = 0; e < PB_PER; e++) {
        int tile = blockIdx.x * PB_PER + e;
        if (tile >= PB_TILES) break;
        int rb = 0, rem = tile;
        while (rem >= (MASK_W - rb)) { rem -= (MASK_W - rb); rb++; }
        int cb = rb + rem;
        if (rb < CHUNKA && cb < CHUNKA) continue;  // phase-A square done
        int row_n = min(PRE_NMS - rb * 64, 64);
        int col_n = min(PRE_NMS - cb * 64, 64);
        __syncthreads();
        if (t < col_n) colb[t] = g_top[cb * 64 + t];
        __syncthreads();
        mask_rows(colb, rb, cb, row_n, col_n, t);
    }

    __threadfence();
    __syncthreads();
    if (t == 0) s_last = (atomicAdd(&g_ctrB, 1) == PB_BLOCKS - 1);
    __syncthreads();
    if (!s_last) return;
    if (t == 0) g_ctrB = 0;
    __threadfence();

    // ---- catchup: OR phase-A (64 chunks) kept rows' words 64..93 ----
    __shared__ ull accw[30];
    __shared__ short rows[CHUNKA * 64];
    __shared__ int s_n;
    __shared__ int s_pick[POST_NMS];
    if (t == 0) s_n = 0;
    if (t < 30) accw[t] = 0ULL;
    __syncthreads();
    if (t < CHUNKA) {
        ull km = g_keptm[t];
        int n = __popcll(km);
        int off = atomicAdd(&s_n, n);
        while (km) {
            int b = __ffsll((long long)km) - 1; km &= km - 1;
            rows[off++] = (short)(t * 64 + b);
        }
    }
    __syncthreads();
    int K = s_n;
    for (int idx = t; idx < K * 30; idx += 64) {
        int rr = idx / 30, w = idx % 30;
        ull v = g_mask[(size_t)rows[rr] * MASK_W + CHUNKA + w];
        if (v) atomicOr(&accw[w], v);
    }
    int np0 = g_np;
    for (int p = t; p < np0; p += 64) s_pick[p] = g_pick[p];
    __syncthreads();

    // ---- scanB: chunks 64..93 (warp 0 only) ----
    if (t < 32) {
        int lane = t;
        int np = np0;
        ull r2 = (lane < 30) ? accw[lane] : 0ULL;       // word 64+lane
        ull f2 = (lane < 30) ? fin_word(CHUNKA + lane) : 0ULL;

        bool done = false;
        for (int c = CHUNKA; c < MASK_W && !done; c++) {
            ull r = __shfl_sync(0xffffffffu, r2, c - CHUNKA);
            ull fw = __shfl_sync(0xffffffffu, f2, c - CHUNKA);

            int nrows = min(PRE_NMS - c * 64, 64);
            ull lim = (nrows == 64) ? ~0ULL : ((1ULL << nrows) - 1ULL);
            ull d0 = (lane < nrows)
                ? g_mask[(size_t)(c * 64 + lane) * MASK_W + c] : 0ULL;
            ull d1 = (lane + 32 < nrows)
                ? g_mask[(size_t)(c * 64 + lane + 32) * MASK_W + c] : 0ULL;

            ull avail = ~r & lim;
            ull keptm = 0ULL;
            while (avail) {
                int b = __ffsll((long long)avail) - 1;
                keptm |= (1ULL << b);
                if ((fw >> b) & 1ULL) {
                    if (lane == 0) s_pick[np] = c * 64 + b;
                    np++;
                    if (np == POST_NMS) { done = true; break; }
                }
                ull dv = __shfl_sync(0xffffffffu, (b < 32) ? d0 : d1, b & 31);
                avail &= ~dv;
                avail &= ~(1ULL << b);
            }

            if (!done) {
                ull km = keptm;
                while (km) {
                    int rr4[4]; int nr = 0;
                    #pragma unroll
                    for (int u = 0; u < 4; u++) {
                        if (km) { rr4[nr++] = __ffsll((long long)km) - 1; km &= km - 1; }
                    }
                    ull a2 = 0;
                    #pragma unroll
                    for (int u = 0; u < 4; u++) {
                        if (u < nr && lane < 30) {
                            a2 |= g_mask[(size_t)(c * 64 + rr4[u]) * MASK_W
                                         + CHUNKA + lane];
                        }
                    }
                    r2 |= a2;
                }
            }
        }

        __syncwarp();
        const float inv = 1.0f / 1024.0f;
        for (int p = lane; p < np; p += 32) {
            int i = s_pick[p];
            float4 b = g_top[i];
            out[p * 4 + 0] = b.x * inv;
            out[p * 4 + 1] = b.y * inv;
            out[p * 4 + 2] = b.z * inv;
            out[p * 4 + 3] = b.w * inv;
        }
    }
}

// ---------------------------------------------------------------------------
extern "C" void kernel_launch(void* const* d_in, const int* in_sizes, int n_in,
                              void* d_out, int out_size) {
    const float* scores = (const float*)d_in[0];
    const float* deltas = (const float*)d_in[1];
    float* out = (float*)d_out;

    k_props<<<NBLK, 1024>>>(scores, deltas);
    k_sort_local<<<2, 1024>>>();
    k_merge_s<<<2, 1024>>>();
    k_maskA_scanA<<<MA_BLOCKS, 256>>>(out);
    k_phaseB<<<PB_BLOCKS, 64>>>(out);
}